// round 2
// baseline (speedup 1.0000x reference)
#include <cuda_runtime.h>
#include <cuda_bf16.h>

#define B_  64
#define Q_  900
#define T_  100
#define C_  256
#define INF_ 1e9f

// Transposed cost scratch [B, T, Q] for contiguous row access in Hungarian.
__device__ float g_costT[B_ * T_ * Q_];

// ---------------------------------------------------------------------------
// Phase 1: cost matrix. grid (ceil(Q/32), B), 256 threads.
// ---------------------------------------------------------------------------
__global__ __launch_bounds__(256) void cost_kernel(
    const float* __restrict__ logits,   // [B,Q,C]
    const float* __restrict__ pboxes,   // [B,Q,4] cxcywh
    const int*   __restrict__ labels,   // [B,T]
    const float* __restrict__ tboxes,   // [B,T,4] cxcywh
    float* __restrict__ cost)           // [B,Q,T]
{
    const int b  = blockIdx.y;
    const int q0 = blockIdx.x * 32;
    const int qcnt = min(32, Q_ - q0);
    const int tid = threadIdx.x;

    __shared__ float slog[32][257];
    __shared__ float stile[32][100];
    __shared__ float stb[100][4];
    __shared__ int   slab[100];
    __shared__ float spb[32][4];

    {
        const float* lg = logits + ((long)b * Q_ + q0) * C_;
        for (int i = tid * 4; i < qcnt * C_; i += 256 * 4) {
            float4 vv = *reinterpret_cast<const float4*>(lg + i);
            int r = i >> 8, c = i & 255;
            slog[r][c + 0] = vv.x; slog[r][c + 1] = vv.y;
            slog[r][c + 2] = vv.z; slog[r][c + 3] = vv.w;
        }
    }
    for (int i = tid; i < T_ * 4; i += 256)
        stb[i >> 2][i & 3] = tboxes[(long)b * T_ * 4 + i];
    for (int i = tid; i < T_; i += 256)
        slab[i] = labels[(long)b * T_ + i];
    for (int i = tid; i < qcnt * 4; i += 256)
        spb[i >> 2][i & 3] = pboxes[((long)b * Q_ + q0) * 4 + i];
    __syncthreads();

    for (int idx = tid; idx < qcnt * T_; idx += 256) {
        int qi = idx / T_;
        int t  = idx - qi * T_;
        float pcx = spb[qi][0], pcy = spb[qi][1], pw = spb[qi][2], ph = spb[qi][3];
        float tcx = stb[t][0],  tcy = stb[t][1],  tw = stb[t][2],  th = stb[t][3];

        float l1 = fabsf(pcx - tcx) + fabsf(pcy - tcy) + fabsf(pw - tw) + fabsf(ph - th);

        float ax0 = pcx - 0.5f * pw, ay0 = pcy - 0.5f * ph;
        float ax1 = pcx + 0.5f * pw, ay1 = pcy + 0.5f * ph;
        float bx0 = tcx - 0.5f * tw, by0 = tcy - 0.5f * th;
        float bx1 = tcx + 0.5f * tw, by1 = tcy + 0.5f * th;

        float areaA = (ax1 - ax0) * (ay1 - ay0);
        float areaB = (bx1 - bx0) * (by1 - by0);
        float ltx = fmaxf(ax0, bx0), lty = fmaxf(ay0, by0);
        float rbx = fminf(ax1, bx1), rby = fminf(ay1, by1);
        float iw = fmaxf(rbx - ltx, 0.f), ih = fmaxf(rby - lty, 0.f);
        float inter = iw * ih;
        float uni = areaA + areaB - inter;
        float iou = inter / uni;
        float ex0 = fminf(ax0, bx0), ey0 = fminf(ay0, by0);
        float ex1 = fmaxf(ax1, bx1), ey1 = fmaxf(ey1 = ay1, by1);
        float enc = fmaxf(ex1 - ex0, 0.f) * fmaxf(ey1 - ey0, 0.f);
        float giou = iou - (enc - uni) / enc;

        float cval = -slog[qi][slab[t]] + l1 - giou;

        stile[qi][t] = cval;
        cost[((long)(b * Q_ + q0 + qi)) * T_ + t] = cval;
    }
    __syncthreads();

    for (int idx = tid; idx < 32 * T_; idx += 256) {
        int qi = idx & 31;
        int t  = idx >> 5;
        if (qi < qcnt)
            g_costT[((long)b * T_ + t) * Q_ + q0 + qi] = stile[qi][t];
    }
}

// ---------------------------------------------------------------------------
// Phase 2: lapjv-style shortest augmenting path. One 256-thread block per
// batch; d/pred-cand/scanned in registers; duals updated once per phase;
// 2 barriers per inner Dijkstra step.
// ---------------------------------------------------------------------------
__global__ __launch_bounds__(256) void hungarian_kernel(float* __restrict__ out)
{
    const int b    = blockIdx.x;
    const int tid  = threadIdx.x;
    const int wid  = tid >> 5, lane = tid & 31;
    const float* CT = g_costT + (long)b * T_ * Q_;

    __shared__ float v[Q_];
    __shared__ int   pred[Q_];
    __shared__ int   y[Q_];      // col -> row (-1 free)
    __shared__ int   x[T_];      // row -> col
    __shared__ float s_mu;
    __shared__ int   s_jstar;
    __shared__ float rv[8];
    __shared__ int   ri[8];
    __shared__ int   col[T_];

    // column ownership: thread owns j = tid + 256*k, k=0..3 (k=3 valid iff tid<132)
    const int nk = (tid < Q_ - 768) ? 4 : 3;

    for (int j = tid; j < Q_; j += 256) { v[j] = 0.f; y[j] = -1; }
    if (tid < T_) x[tid] = -1;
    __syncthreads();

    for (int f = 0; f < T_; f++) {
        float d[4]  = {INF_, INF_, INF_, INF_};
        int   sc[4] = {0, 0, 0, 0};
        int   i1 = f;
        float h  = 0.f;
        const float* crow = CT + (long)f * Q_;
        float mu; int jstar;

        while (true) {
            // scan + local argmin over unscanned owned columns
            float bv = INF_; int bj = 0x7fffffff;
            #pragma unroll
            for (int k = 0; k < 4; k++) {
                if (k < nk && !sc[k]) {
                    int j = tid + (k << 8);
                    float nd = __ldg(crow + j) - v[j] - h;
                    if (nd < d[k]) { d[k] = nd; pred[j] = i1; }
                    if (d[k] < bv) { bv = d[k]; bj = j; }
                }
            }
            // warp argmin (lowest index on ties)
            #pragma unroll
            for (int off = 16; off; off >>= 1) {
                float v2 = __shfl_down_sync(0xffffffffu, bv, off);
                int   j2 = __shfl_down_sync(0xffffffffu, bj, off);
                if (v2 < bv || (v2 == bv && j2 < bj)) { bv = v2; bj = j2; }
            }
            if (lane == 0) { rv[wid] = bv; ri[wid] = bj; }
            __syncthreads();
            if (wid == 0) {
                float fv = (lane < 8) ? rv[lane] : INF_;
                int   fj = (lane < 8) ? ri[lane] : 0x7fffffff;
                #pragma unroll
                for (int off = 4; off; off >>= 1) {
                    float v2 = __shfl_down_sync(0xffffffffu, fv, off);
                    int   j2 = __shfl_down_sync(0xffffffffu, fj, off);
                    if (v2 < fv || (v2 == fv && j2 < fj)) { fv = v2; fj = j2; }
                }
                if (lane == 0) { s_mu = fv; s_jstar = fj; }
            }
            __syncthreads();

            mu = s_mu; jstar = s_jstar;
            i1 = y[jstar];
            if (i1 < 0) break;                    // free column found (uniform)

            if ((jstar & 255) == tid) sc[jstar >> 8] = 1;   // owner marks scanned
            crow = CT + (long)i1 * Q_;
            h = __ldg(crow + jstar) - v[jstar] - mu;        // broadcast load, all threads
        }

        // dual update on scanned columns only
        #pragma unroll
        for (int k = 0; k < 4; k++)
            if (sc[k]) { int j = tid + (k << 8); v[j] += d[k] - mu; }

        // augment (serial pointer chase, short)
        if (tid == 0) {
            int j = jstar;
            while (true) {
                int i = pred[j];
                y[j] = i;
                int jn = x[i];
                x[i] = j;
                if (i == f) break;
                j = jn;
            }
        }
        __syncthreads();
    }

    // col[t] = query assigned to target t
    for (int j = tid; j < Q_; j += 256) {
        int r = y[j];
        if (r >= 0) col[r] = j;
    }
    __syncthreads();

    if (tid < T_) {
        int c = col[tid];
        int r = 0;
        #pragma unroll 4
        for (int t2 = 0; t2 < T_; t2++) r += (col[t2] < c);
        const long base = (long)B_ * Q_ * T_;
        out[base + (long)b * T_ + r] = (float)c;                    // pred_idx
        out[base + (long)B_ * T_ + (long)b * T_ + r] = (float)tid;  // tgt_idx
    }
}

extern "C" void kernel_launch(void* const* d_in, const int* in_sizes, int n_in,
                              void* d_out, int out_size)
{
    const float* pred_logits = (const float*)d_in[0];
    const float* pred_boxes  = (const float*)d_in[1];
    const int*   tgt_labels  = (const int*)d_in[2];
    const float* tgt_boxes   = (const float*)d_in[3];
    float* out = (float*)d_out;

    dim3 grid1((Q_ + 31) / 32, B_);
    cost_kernel<<<grid1, 256>>>(pred_logits, pred_boxes, tgt_labels, tgt_boxes, out);
    hungarian_kernel<<<B_, 256>>>(out);
}

// round 3
// speedup vs baseline: 2.4272x; 2.4272x over previous
#include <cuda_runtime.h>
#include <cuda_bf16.h>

#define B_  64
#define Q_  900
#define T_  100
#define C_  256
#define INF_ 1e9f

// Transposed cost scratch [B, T, Q] for contiguous row access in Hungarian.
__device__ float g_costT[B_ * T_ * Q_];
// Per (b, target-row) packed min: [orderable-float-key:32 | col-index:32]
__device__ unsigned long long g_rowmin[B_ * T_];

__global__ void init_rowmin() {
    int i = blockIdx.x * blockDim.x + threadIdx.x;
    if (i < B_ * T_) g_rowmin[i] = ~0ULL;
}

__device__ __forceinline__ unsigned int f32_orderable(float f) {
    unsigned int b = __float_as_uint(f);
    return (b & 0x80000000u) ? ~b : (b | 0x80000000u);
}

// ---------------------------------------------------------------------------
// Phase 1: cost matrix + fused per-target-row argmin. grid (29, B), 256 thr.
// ---------------------------------------------------------------------------
__global__ __launch_bounds__(256) void cost_kernel(
    const float* __restrict__ logits,   // [B,Q,C]
    const float* __restrict__ pboxes,   // [B,Q,4] cxcywh
    const int*   __restrict__ labels,   // [B,T]
    const float* __restrict__ tboxes,   // [B,T,4] cxcywh
    float* __restrict__ cost)           // [B,Q,T]
{
    const int b  = blockIdx.y;
    const int q0 = blockIdx.x * 32;
    const int qcnt = min(32, Q_ - q0);
    const int tid = threadIdx.x;

    __shared__ float slog[32][257];
    __shared__ float stile[32][100];
    __shared__ float stb[100][4];
    __shared__ int   slab[100];
    __shared__ float spb[32][4];

    {
        const float* lg = logits + ((long)b * Q_ + q0) * C_;
        for (int i = tid * 4; i < qcnt * C_; i += 256 * 4) {
            float4 vv = *reinterpret_cast<const float4*>(lg + i);
            int r = i >> 8, c = i & 255;
            slog[r][c + 0] = vv.x; slog[r][c + 1] = vv.y;
            slog[r][c + 2] = vv.z; slog[r][c + 3] = vv.w;
        }
    }
    for (int i = tid; i < T_ * 4; i += 256)
        stb[i >> 2][i & 3] = tboxes[(long)b * T_ * 4 + i];
    for (int i = tid; i < T_; i += 256)
        slab[i] = labels[(long)b * T_ + i];
    for (int i = tid; i < qcnt * 4; i += 256)
        spb[i >> 2][i & 3] = pboxes[((long)b * Q_ + q0) * 4 + i];
    __syncthreads();

    for (int idx = tid; idx < qcnt * T_; idx += 256) {
        int qi = idx / T_;
        int t  = idx - qi * T_;
        float pcx = spb[qi][0], pcy = spb[qi][1], pw = spb[qi][2], ph = spb[qi][3];
        float tcx = stb[t][0],  tcy = stb[t][1],  tw = stb[t][2],  th = stb[t][3];

        float l1 = fabsf(pcx - tcx) + fabsf(pcy - tcy) + fabsf(pw - tw) + fabsf(ph - th);

        float ax0 = pcx - 0.5f * pw, ay0 = pcy - 0.5f * ph;
        float ax1 = pcx + 0.5f * pw, ay1 = pcy + 0.5f * ph;
        float bx0 = tcx - 0.5f * tw, by0 = tcy - 0.5f * th;
        float bx1 = tcx + 0.5f * tw, by1 = tcy + 0.5f * th;

        float areaA = (ax1 - ax0) * (ay1 - ay0);
        float areaB = (bx1 - bx0) * (by1 - by0);
        float ltx = fmaxf(ax0, bx0), lty = fmaxf(ay0, by0);
        float rbx = fminf(ax1, bx1), rby = fminf(ay1, by1);
        float iw = fmaxf(rbx - ltx, 0.f), ih = fmaxf(rby - lty, 0.f);
        float inter = iw * ih;
        float uni = areaA + areaB - inter;
        float iou = inter / uni;
        float ex0 = fminf(ax0, bx0), ey0 = fminf(ay0, by0);
        float ex1 = fmaxf(ax1, bx1), ey1 = fmaxf(ay1, by1);
        float enc = fmaxf(ex1 - ex0, 0.f) * fmaxf(ey1 - ey0, 0.f);
        float giou = iou - (enc - uni) / enc;

        float cval = -slog[qi][slab[t]] + l1 - giou;

        stile[qi][t] = cval;
        cost[((long)(b * Q_ + q0 + qi)) * T_ + t] = cval;
    }
    __syncthreads();

    // per-target-row argmin over this q-chunk -> global packed atomicMin
    if (tid < T_) {
        float best = INF_; int bq = 0;
        for (int qi = 0; qi < qcnt; qi++) {
            float c = stile[qi][tid];
            if (c < best) { best = c; bq = q0 + qi; }
        }
        unsigned long long packed =
            ((unsigned long long)f32_orderable(best) << 32) | (unsigned int)bq;
        atomicMin(&g_rowmin[b * T_ + tid], packed);
    }

    // transposed write (coalesced over qi)
    for (int idx = tid; idx < 32 * T_; idx += 256) {
        int qi = idx & 31;
        int t  = idx >> 5;
        if (qi < qcnt)
            g_costT[((long)b * T_ + t) * Q_ + q0 + qi] = stile[qi][t];
    }
}

// ---------------------------------------------------------------------------
// Phase 2: JV with greedy row-reduction init; shortest-augmenting-path only
// for the ~6 conflicted rows. One 256-thread block per batch; each thread
// owns a contiguous float4 of the 900 columns.
// ---------------------------------------------------------------------------
__global__ __launch_bounds__(256) void hungarian_kernel(float* __restrict__ out)
{
    const int b    = blockIdx.x;
    const int tid  = threadIdx.x;
    const int wid  = tid >> 5, lane = tid & 31;
    const float* CT = g_costT + (long)b * T_ * Q_;
    const bool owns = (tid < Q_ / 4);   // 225 scan threads, 4 contiguous cols each

    __shared__ float v[Q_];
    __shared__ int   pred[Q_];
    __shared__ int   y[Q_];      // col -> row (-1 free)
    __shared__ int   x[T_];      // row -> col
    __shared__ float s_mu;
    __shared__ int   s_jstar;
    __shared__ float rv[8];
    __shared__ int   ri[8];
    __shared__ int   col[T_];
    __shared__ int   freeRows[T_];
    __shared__ int   s_nfree;

    for (int j = tid; j < Q_; j += 256) { v[j] = 0.f; y[j] = -1; }
    __syncthreads();

    // greedy row reduction: assign rows whose argmin column is still free
    if (tid == 0) {
        int nf = 0;
        for (int i = 0; i < T_; i++) {
            int j = (int)(unsigned int)(g_rowmin[b * T_ + i] & 0xFFFFFFFFULL);
            if (y[j] < 0) { y[j] = i; x[i] = j; }
            else          { x[i] = -1; freeRows[nf++] = i; }
        }
        s_nfree = nf;
    }
    __syncthreads();
    const int nfree = s_nfree;

    for (int fi = 0; fi < nfree; fi++) {
        const int f = freeRows[fi];
        float4 d = make_float4(INF_, INF_, INF_, INF_);
        unsigned int scm = 0;              // scanned bitmask for my 4 columns
        int   i1 = f;
        float h  = 0.f;
        const float* crow = CT + (long)f * Q_;
        float mu; int jstar;

        while (true) {
            float bv = INF_; int bj = 0x7fffffff;
            if (owns) {
                const int j0 = tid << 2;
                float4 cv = __ldg((const float4*)(crow) + tid);
                float4 vv = *((const float4*)v + tid);
                if (!(scm & 1u)) {
                    float nd = cv.x - vv.x - h;
                    if (nd < d.x) { d.x = nd; pred[j0 + 0] = i1; }
                    if (d.x < bv) { bv = d.x; bj = j0 + 0; }
                }
                if (!(scm & 2u)) {
                    float nd = cv.y - vv.y - h;
                    if (nd < d.y) { d.y = nd; pred[j0 + 1] = i1; }
                    if (d.y < bv) { bv = d.y; bj = j0 + 1; }
                }
                if (!(scm & 4u)) {
                    float nd = cv.z - vv.z - h;
                    if (nd < d.z) { d.z = nd; pred[j0 + 2] = i1; }
                    if (d.z < bv) { bv = d.z; bj = j0 + 2; }
                }
                if (!(scm & 8u)) {
                    float nd = cv.w - vv.w - h;
                    if (nd < d.w) { d.w = nd; pred[j0 + 3] = i1; }
                    if (d.w < bv) { bv = d.w; bj = j0 + 3; }
                }
            }
            #pragma unroll
            for (int off = 16; off; off >>= 1) {
                float v2 = __shfl_down_sync(0xffffffffu, bv, off);
                int   j2 = __shfl_down_sync(0xffffffffu, bj, off);
                if (v2 < bv || (v2 == bv && j2 < bj)) { bv = v2; bj = j2; }
            }
            if (lane == 0) { rv[wid] = bv; ri[wid] = bj; }
            __syncthreads();
            if (wid == 0) {
                float fv = (lane < 8) ? rv[lane] : INF_;
                int   fj = (lane < 8) ? ri[lane] : 0x7fffffff;
                #pragma unroll
                for (int off = 4; off; off >>= 1) {
                    float v2 = __shfl_down_sync(0xffffffffu, fv, off);
                    int   j2 = __shfl_down_sync(0xffffffffu, fj, off);
                    if (v2 < fv || (v2 == fv && j2 < fj)) { fv = v2; fj = j2; }
                }
                if (lane == 0) { s_mu = fv; s_jstar = fj; }
            }
            __syncthreads();

            mu = s_mu; jstar = s_jstar;
            i1 = y[jstar];
            if (i1 < 0) break;                       // free column: path found

            if ((jstar >> 2) == tid) scm |= 1u << (jstar & 3);
            crow = CT + (long)i1 * Q_;
            h = __ldg(crow + jstar) - v[jstar] - mu; // broadcast; overlaps scan loads
        }

        // dual update on scanned (in-tree) columns
        if (owns) {
            const int j0 = tid << 2;
            if (scm & 1u) v[j0 + 0] += d.x - mu;
            if (scm & 2u) v[j0 + 1] += d.y - mu;
            if (scm & 4u) v[j0 + 2] += d.z - mu;
            if (scm & 8u) v[j0 + 3] += d.w - mu;
        }

        // augment along predecessor chain
        if (tid == 0) {
            int j = jstar;
            while (true) {
                int i = pred[j];
                y[j] = i;
                int jn = x[i];
                x[i] = j;
                if (i == f) break;
                j = jn;
            }
        }
        __syncthreads();
    }

    // col[t] = query assigned to target t
    for (int j = tid; j < Q_; j += 256) {
        int r = y[j];
        if (r >= 0) col[r] = j;
    }
    __syncthreads();

    // rank = argsort(col) -> pred_idx sorted ascending with matching tgt_idx
    if (tid < T_) {
        int c = col[tid];
        int r = 0;
        #pragma unroll 4
        for (int t2 = 0; t2 < T_; t2++) r += (col[t2] < c);
        const long base = (long)B_ * Q_ * T_;
        out[base + (long)b * T_ + r] = (float)c;                    // pred_idx
        out[base + (long)B_ * T_ + (long)b * T_ + r] = (float)tid;  // tgt_idx
    }
}

extern "C" void kernel_launch(void* const* d_in, const int* in_sizes, int n_in,
                              void* d_out, int out_size)
{
    const float* pred_logits = (const float*)d_in[0];
    const float* pred_boxes  = (const float*)d_in[1];
    const int*   tgt_labels  = (const int*)d_in[2];
    const float* tgt_boxes   = (const float*)d_in[3];
    float* out = (float*)d_out;

    init_rowmin<<<(B_ * T_ + 1023) / 1024, 1024>>>();
    dim3 grid1((Q_ + 31) / 32, B_);
    cost_kernel<<<grid1, 256>>>(pred_logits, pred_boxes, tgt_labels, tgt_boxes, out);
    hungarian_kernel<<<B_, 256>>>(out);
}

// round 4
// speedup vs baseline: 2.5491x; 1.0502x over previous
#include <cuda_runtime.h>
#include <cuda_bf16.h>

#define B_  64
#define Q_  900
#define T_  100
#define C_  256
#define INF_ 1e9f
#define NCH 29   // ceil(Q_/32)

// Transposed cost scratch [B, T, Q] for contiguous row access in Hungarian.
__device__ float g_costT[B_ * T_ * Q_];
// Per (b, chunk, target-row) packed partial min: [orderable-key:32 | col:32]
__device__ unsigned long long g_rowpart[B_ * NCH * T_];

__device__ __forceinline__ unsigned int f32_orderable(float f) {
    unsigned int b = __float_as_uint(f);
    return (b & 0x80000000u) ? ~b : (b | 0x80000000u);
}

// ---------------------------------------------------------------------------
// Phase 1: cost matrix + per-chunk target-row argmin. grid (29, B), 256 thr.
// ---------------------------------------------------------------------------
__global__ __launch_bounds__(256) void cost_kernel(
    const float* __restrict__ logits,   // [B,Q,C]
    const float* __restrict__ pboxes,   // [B,Q,4] cxcywh
    const int*   __restrict__ labels,   // [B,T]
    const float* __restrict__ tboxes,   // [B,T,4] cxcywh
    float* __restrict__ cost)           // [B,Q,T]
{
    const int b  = blockIdx.y;
    const int q0 = blockIdx.x * 32;
    const int qcnt = min(32, Q_ - q0);
    const int tid = threadIdx.x;

    __shared__ float slog[32][257];
    __shared__ float stile[32][100];
    __shared__ float stb[100][4];
    __shared__ int   slab[100];
    __shared__ float spb[32][4];

    {
        const float* lg = logits + ((long)b * Q_ + q0) * C_;
        for (int i = tid * 4; i < qcnt * C_; i += 256 * 4) {
            float4 vv = *reinterpret_cast<const float4*>(lg + i);
            int r = i >> 8, c = i & 255;
            slog[r][c + 0] = vv.x; slog[r][c + 1] = vv.y;
            slog[r][c + 2] = vv.z; slog[r][c + 3] = vv.w;
        }
    }
    for (int i = tid; i < T_ * 4; i += 256)
        stb[i >> 2][i & 3] = tboxes[(long)b * T_ * 4 + i];
    for (int i = tid; i < T_; i += 256)
        slab[i] = labels[(long)b * T_ + i];
    for (int i = tid; i < qcnt * 4; i += 256)
        spb[i >> 2][i & 3] = pboxes[((long)b * Q_ + q0) * 4 + i];
    __syncthreads();

    for (int idx = tid; idx < qcnt * T_; idx += 256) {
        int qi = idx / T_;
        int t  = idx - qi * T_;
        float pcx = spb[qi][0], pcy = spb[qi][1], pw = spb[qi][2], ph = spb[qi][3];
        float tcx = stb[t][0],  tcy = stb[t][1],  tw = stb[t][2],  th = stb[t][3];

        float l1 = fabsf(pcx - tcx) + fabsf(pcy - tcy) + fabsf(pw - tw) + fabsf(ph - th);

        float ax0 = pcx - 0.5f * pw, ay0 = pcy - 0.5f * ph;
        float ax1 = pcx + 0.5f * pw, ay1 = pcy + 0.5f * ph;
        float bx0 = tcx - 0.5f * tw, by0 = tcy - 0.5f * th;
        float bx1 = tcx + 0.5f * tw, by1 = tcy + 0.5f * th;

        float areaA = (ax1 - ax0) * (ay1 - ay0);
        float areaB = (bx1 - bx0) * (by1 - by0);
        float ltx = fmaxf(ax0, bx0), lty = fmaxf(ay0, by0);
        float rbx = fminf(ax1, bx1), rby = fminf(ay1, by1);
        float iw = fmaxf(rbx - ltx, 0.f), ih = fmaxf(rby - lty, 0.f);
        float inter = iw * ih;
        float uni = areaA + areaB - inter;
        float iou = inter / uni;
        float ex0 = fminf(ax0, bx0), ey0 = fminf(ay0, by0);
        float ex1 = fmaxf(ax1, bx1), ey1 = fmaxf(ay1, by1);
        float enc = fmaxf(ex1 - ex0, 0.f) * fmaxf(ey1 - ey0, 0.f);
        float giou = iou - (enc - uni) / enc;

        float cval = -slog[qi][slab[t]] + l1 - giou;

        stile[qi][t] = cval;
        cost[((long)(b * Q_ + q0 + qi)) * T_ + t] = cval;
    }
    __syncthreads();

    // per-chunk target-row argmin -> packed partial (no atomics)
    if (tid < T_) {
        float best = INF_; int bq = 0;
        for (int qi = 0; qi < qcnt; qi++) {
            float c = stile[qi][tid];
            if (c < best) { best = c; bq = q0 + qi; }
        }
        g_rowpart[((long)b * NCH + blockIdx.x) * T_ + tid] =
            ((unsigned long long)f32_orderable(best) << 32) | (unsigned int)bq;
    }

    // transposed write (coalesced over qi)
    for (int idx = tid; idx < 32 * T_; idx += 256) {
        int qi = idx & 31;
        int t  = idx >> 5;
        if (qi < qcnt)
            g_costT[((long)b * T_ + t) * Q_ + q0 + qi] = stile[qi][t];
    }
}

// ---------------------------------------------------------------------------
// Phase 2: JV with greedy row-reduction init; shortest augmenting path only
// for conflicted rows. One 256-thread block per batch. 1 barrier/iteration.
// ---------------------------------------------------------------------------
__global__ __launch_bounds__(256) void hungarian_kernel(float* __restrict__ out)
{
    const int b    = blockIdx.x;
    const int tid  = threadIdx.x;
    const int wid  = tid >> 5, lane = tid & 31;
    const float* CT = g_costT + (long)b * T_ * Q_;
    const bool owns = (tid < Q_ / 4);   // 225 scan threads, 4 contiguous cols each

    __shared__ float v[Q_];
    __shared__ int   pred[Q_];
    __shared__ int   y[Q_];      // col -> row (-1 free)
    __shared__ int   x[T_];      // row -> col
    __shared__ float rv[2][8];
    __shared__ int   ri[2][8];
    __shared__ int   col[T_];
    __shared__ int   rmin[T_];   // argmin col per target row
    __shared__ int   freeRows[T_];
    __shared__ int   s_nfree;

    for (int j = tid; j < Q_; j += 256) { v[j] = 0.f; y[j] = -1; }

    // parallel reduction of per-chunk partial argmins (coalesced over t)
    if (tid < T_) {
        const unsigned long long* rp = g_rowpart + (long)b * NCH * T_ + tid;
        unsigned long long m = rp[0];
        #pragma unroll
        for (int c = 1; c < NCH; c++) {
            unsigned long long pk = rp[(long)c * T_];
            if (pk < m) m = pk;
        }
        rmin[tid] = (int)(unsigned int)(m & 0xFFFFFFFFULL);
    }
    __syncthreads();

    // greedy: assign rows whose argmin column is still free (serial, shared only)
    if (tid == 0) {
        int nf = 0;
        for (int i = 0; i < T_; i++) {
            int j = rmin[i];
            if (y[j] < 0) { y[j] = i; x[i] = j; }
            else          { x[i] = -1; freeRows[nf++] = i; }
        }
        s_nfree = nf;
    }
    __syncthreads();
    const int nfree = s_nfree;

    for (int fi = 0; fi < nfree; fi++) {
        const int f = freeRows[fi];
        float4 d = make_float4(INF_, INF_, INF_, INF_);
        unsigned int scm = 0;              // scanned bitmask for my 4 columns
        int   i1 = f;
        float h  = 0.f;
        const float* crow = CT + (long)f * Q_;
        float mu; int jstar;
        int pp = 0;

        while (true) {
            float bv = INF_; int bj = 0x7fffffff;
            if (owns) {
                const int j0 = tid << 2;
                float4 cv = __ldg((const float4*)(crow) + tid);
                float4 vv = *((const float4*)v + tid);
                if (!(scm & 1u)) {
                    float nd = cv.x - vv.x - h;
                    if (nd < d.x) { d.x = nd; pred[j0 + 0] = i1; }
                    if (d.x < bv) { bv = d.x; bj = j0 + 0; }
                }
                if (!(scm & 2u)) {
                    float nd = cv.y - vv.y - h;
                    if (nd < d.y) { d.y = nd; pred[j0 + 1] = i1; }
                    if (d.y < bv) { bv = d.y; bj = j0 + 1; }
                }
                if (!(scm & 4u)) {
                    float nd = cv.z - vv.z - h;
                    if (nd < d.z) { d.z = nd; pred[j0 + 2] = i1; }
                    if (d.z < bv) { bv = d.z; bj = j0 + 2; }
                }
                if (!(scm & 8u)) {
                    float nd = cv.w - vv.w - h;
                    if (nd < d.w) { d.w = nd; pred[j0 + 3] = i1; }
                    if (d.w < bv) { bv = d.w; bj = j0 + 3; }
                }
            }
            #pragma unroll
            for (int off = 16; off; off >>= 1) {
                float v2 = __shfl_down_sync(0xffffffffu, bv, off);
                int   j2 = __shfl_down_sync(0xffffffffu, bj, off);
                if (v2 < bv || (v2 == bv && j2 < bj)) { bv = v2; bj = j2; }
            }
            if (lane == 0) { rv[pp][wid] = bv; ri[pp][wid] = bj; }
            __syncthreads();                       // the ONLY barrier per iter

            // every thread reduces the 8 warp results (identical, deterministic)
            mu = rv[pp][0]; jstar = ri[pp][0];
            #pragma unroll
            for (int k = 1; k < 8; k++) {
                float v2 = rv[pp][k]; int j2 = ri[pp][k];
                if (v2 < mu || (v2 == mu && j2 < jstar)) { mu = v2; jstar = j2; }
            }
            i1 = y[jstar];
            if (i1 < 0) break;                     // free column: path found

            if ((jstar >> 2) == tid) scm |= 1u << (jstar & 3);
            crow = CT + (long)i1 * Q_;
            h = __ldg(crow + jstar) - v[jstar] - mu;
            pp ^= 1;
        }
        __syncthreads();   // everyone done reading y before augment mutates it

        // dual update on scanned (in-tree) columns
        if (owns) {
            const int j0 = tid << 2;
            if (scm & 1u) v[j0 + 0] += d.x - mu;
            if (scm & 2u) v[j0 + 1] += d.y - mu;
            if (scm & 4u) v[j0 + 2] += d.z - mu;
            if (scm & 8u) v[j0 + 3] += d.w - mu;
        }

        // augment along predecessor chain
        if (tid == 0) {
            int j = jstar;
            while (true) {
                int i = pred[j];
                y[j] = i;
                int jn = x[i];
                x[i] = j;
                if (i == f) break;
                j = jn;
            }
        }
        __syncthreads();
    }

    // col[t] = query assigned to target t
    for (int j = tid; j < Q_; j += 256) {
        int r = y[j];
        if (r >= 0) col[r] = j;
    }
    __syncthreads();

    // rank = argsort(col) -> pred_idx sorted ascending with matching tgt_idx
    if (tid < T_) {
        int c = col[tid];
        int r = 0;
        #pragma unroll 4
        for (int t2 = 0; t2 < T_; t2++) r += (col[t2] < c);
        const long base = (long)B_ * Q_ * T_;
        out[base + (long)b * T_ + r] = (float)c;                    // pred_idx
        out[base + (long)B_ * T_ + (long)b * T_ + r] = (float)tid;  // tgt_idx
    }
}

extern "C" void kernel_launch(void* const* d_in, const int* in_sizes, int n_in,
                              void* d_out, int out_size)
{
    const float* pred_logits = (const float*)d_in[0];
    const float* pred_boxes  = (const float*)d_in[1];
    const int*   tgt_labels  = (const int*)d_in[2];
    const float* tgt_boxes   = (const float*)d_in[3];
    float* out = (float*)d_out;

    dim3 grid1(NCH, B_);
    cost_kernel<<<grid1, 256>>>(pred_logits, pred_boxes, tgt_labels, tgt_boxes, out);
    hungarian_kernel<<<B_, 256>>>(out);
}